// round 8
// baseline (speedup 1.0000x reference)
#include <cuda_runtime.h>
#include <math.h>
#include <stdint.h>
#include <float.h>

#define BSZ 8
#define TT  8192
#define FF  1024
#define HH  256
#define OO  2
#define MTOK (BSZ * TT)   // 65536 tokens
#define NCHUNK 64

// ---- scratch (static device globals; no runtime allocation) ----
__device__ float  g_h[(size_t)MTOK * HH];     // 64 MB fp32 h (K3 pooling)
__device__ uint4  g_hb4[(size_t)MTOK * 32];   // 32 MB bf16 h, layout [mblk][kp 128][m 128]
__device__ float  g_logit[MTOK];
__device__ float2 g_stat[BSZ];
__device__ float  g_part[BSZ * NCHUNK * HH];
__device__ float  g_slide[BSZ * HH];
__device__ uint4  g_w1s[32 * 1024];           // 512 KB: W1 bf16 [kt 32][kp 16][n 256]
__device__ uint4  g_wvs[16 * 512];            // 128 KB: Wv bf16 [blk 16][kp 32][n 64]
__device__ uint4  g_wus[16 * 512];            // 128 KB: Wu

// ---- helpers ----
__device__ __forceinline__ uint32_t pbf(float lo, float hi) {
    uint32_t r; asm("cvt.rn.bf16x2.f32 %0, %1, %2;" : "=r"(r) : "f"(hi), "f"(lo)); return r;
}
__device__ __forceinline__ float tanhfast(float x) {
    float y; asm("tanh.approx.f32 %0, %1;" : "=f"(y) : "f"(x)); return y;
}
__device__ __forceinline__ void mma16(float4& d, const uint32_t* a, uint32_t b0, uint32_t b1) {
    asm volatile("mma.sync.aligned.m16n8k16.row.col.f32.bf16.bf16.f32 "
        "{%0,%1,%2,%3}, {%4,%5,%6,%7}, {%8,%9}, {%0,%1,%2,%3};"
        : "+f"(d.x), "+f"(d.y), "+f"(d.z), "+f"(d.w)
        : "r"(a[0]), "r"(a[1]), "r"(a[2]), "r"(a[3]), "r"(b0), "r"(b1));
}
__device__ __forceinline__ uint32_t s2u(const void* p) {
    uint32_t a; asm("{ .reg .u64 t; cvta.to.shared.u64 t, %1; cvt.u32.u64 %0, t; }" : "=r"(a) : "l"(p));
    return a;
}
__device__ __forceinline__ void cpa16(uint32_t dst, const void* src) {
    asm volatile("cp.async.cg.shared.global [%0], [%1], 16;" :: "r"(dst), "l"(src));
}
__device__ __forceinline__ void cp_commit() { asm volatile("cp.async.commit_group;"); }
__device__ __forceinline__ void cp_wait0()  { asm volatile("cp.async.wait_group 0;"); }
__device__ __forceinline__ void cp_wait1()  { asm volatile("cp.async.wait_group 1;"); }

// ============================================================================
// k1pre: W1 [1024,256] fp32 -> bf16 images [kt 32][kp 16][n 256].
// word(kt,kp,n) = {W1[kt*32+2kp][n], W1[kt*32+2kp+1][n]}
// ============================================================================
__global__ __launch_bounds__(256)
void k1pre(const float* __restrict__ W1)
{
    const int kt = blockIdx.x, tid = threadIdx.x;
    const int kp = tid >> 4, n16 = (tid & 15) << 4;
    const float* r0 = W1 + (size_t)(kt * 32 + 2 * kp) * HH + n16;
    const float* r1 = r0 + HH;
    uint32_t* dst = (uint32_t*)g_w1s + (size_t)kt * 4096 + kp * 256 + n16;
    #pragma unroll
    for (int j = 0; j < 16; j += 4) {
        const float4 a = *(const float4*)(r0 + j);
        const float4 b = *(const float4*)(r1 + j);
        *(uint4*)(dst + j) = make_uint4(pbf(a.x, b.x), pbf(a.y, b.y), pbf(a.z, b.z), pbf(a.w, b.w));
    }
}

// ============================================================================
// k2pre: Wv/Wu -> bf16 images [blk=nb*4+kh][kp 32][n 64] (R6-proven layout).
// ============================================================================
__global__ __launch_bounds__(256)
void k2pre(const float* __restrict__ Wv, const float* __restrict__ Wu)
{
    const int blk = blockIdx.x, tid = threadIdx.x;
    const int nb = blk >> 2, kh = blk & 3;
    const int kp = tid >> 3, n8 = (tid & 7) << 3;
    const size_t off = (size_t)(kh * 64 + 2 * kp) * HH + nb * 64 + n8;
    {
        const float4 a0 = *(const float4*)(Wv + off),      a1 = *(const float4*)(Wv + off + 4);
        const float4 b0 = *(const float4*)(Wv + off + HH), b1 = *(const float4*)(Wv + off + HH + 4);
        g_wvs[blk * 512 + kp * 16 + (n8 >> 2)] =
            make_uint4(pbf(a0.x, b0.x), pbf(a0.y, b0.y), pbf(a0.z, b0.z), pbf(a0.w, b0.w));
        g_wvs[blk * 512 + kp * 16 + (n8 >> 2) + 1] =
            make_uint4(pbf(a1.x, b1.x), pbf(a1.y, b1.y), pbf(a1.z, b1.z), pbf(a1.w, b1.w));
    }
    {
        const float4 a0 = *(const float4*)(Wu + off),      a1 = *(const float4*)(Wu + off + 4);
        const float4 b0 = *(const float4*)(Wu + off + HH), b1 = *(const float4*)(Wu + off + HH + 4);
        g_wus[blk * 512 + kp * 16 + (n8 >> 2)] =
            make_uint4(pbf(a0.x, b0.x), pbf(a0.y, b0.y), pbf(a0.z, b0.z), pbf(a0.w, b0.w));
        g_wus[blk * 512 + kp * 16 + (n8 >> 2) + 1] =
            make_uint4(pbf(a1.x, b1.x), pbf(a1.y, b1.y), pbf(a1.z, b1.z), pbf(a1.w, b1.w));
    }
}

// ============================================================================
// K1: h = relu(bags @ W1 + b1). CTA 128x256, 512 thr, K-chunks of 32,
// double-buffered; B staged via cp.async from g_w1s, A via regs+STS.
// ============================================================================
#define K1_LDA 136
#define K1_LDB 264
#define K1_AW  (16 * K1_LDA)    // 2176 words per A stage
#define K1_BW  (16 * K1_LDB)    // 4224 words per B stage
#define K1_SMEM ((2 * K1_AW + 2 * K1_BW) * 4)   // 51200 B
__global__ __launch_bounds__(512, 1)
void k1_gemm_relu(const float* __restrict__ A, const float* __restrict__ bias)
{
    extern __shared__ uint32_t sm1[];
    uint32_t* As = sm1;                 // [2][16][136]
    uint32_t* Bs = sm1 + 2 * K1_AW;     // [2][16][264]
    const uint32_t sB = s2u(Bs);

    const int tid = threadIdx.x;
    const int lane = tid & 31, wid = tid >> 5;
    const int wm = wid & 3, wn = wid >> 2;
    const int g = lane >> 2, tg = lane & 3;
    const size_t mBase = (size_t)blockIdx.x * 128;

    const int am = tid & 127, kg = tid >> 7;          // A: row, 8k-group
    const float* aP = A + (mBase + am) * FF + kg * 8;
    const char* bImg = (const char*)g_w1s;
    const int c0 = tid * 2;

    float4 acc[2][8];
    #pragma unroll
    for (int i = 0; i < 2; i++)
        #pragma unroll
        for (int j = 0; j < 8; j++) acc[i][j] = make_float4(0.f, 0.f, 0.f, 0.f);

    float4 ra0, ra1;
    auto ldA = [&](int kt) {
        ra0 = *(const float4*)(aP + kt * 32);
        ra1 = *(const float4*)(aP + kt * 32 + 4);
    };
    auto stA = [&](int p) {
        uint32_t* d = As + p * K1_AW;
        const int kp0 = kg * 4;
        d[(kp0 + 0) * K1_LDA + am] = pbf(ra0.x, ra0.y);
        d[(kp0 + 1) * K1_LDA + am] = pbf(ra0.z, ra0.w);
        d[(kp0 + 2) * K1_LDA + am] = pbf(ra1.x, ra1.y);
        d[(kp0 + 3) * K1_LDA + am] = pbf(ra1.z, ra1.w);
    };
    auto cpB = [&](int kt, int p) {
        #pragma unroll
        for (int j = 0; j < 2; j++) {
            const int c = c0 + j;
            const int row = c >> 6, col = c & 63;
            cpa16(sB + p * (K1_BW * 4) + row * (K1_LDB * 4) + col * 16,
                  bImg + (size_t)kt * 16384 + (size_t)c * 16);
        }
    };

    ldA(0); cpB(0, 0); cp_commit(); stA(0);
    cp_wait0(); __syncthreads();

    for (int kt = 0; kt < 32; kt++) {
        const int p = kt & 1;
        if (kt < 31) { cpB(kt + 1, p ^ 1); cp_commit(); ldA(kt + 1); }

        const uint32_t* ap = As + p * K1_AW;
        const uint32_t* bp = Bs + p * K1_BW;
        #pragma unroll
        for (int ks = 0; ks < 2; ks++) {
            const int r = ks * 8 + tg;
            uint32_t afr[2][4];
            #pragma unroll
            for (int fm = 0; fm < 2; fm++) {
                const int m = wm * 32 + fm * 16 + g;
                afr[fm][0] = ap[r * K1_LDA + m];       afr[fm][1] = ap[r * K1_LDA + m + 8];
                afr[fm][2] = ap[(r + 4) * K1_LDA + m]; afr[fm][3] = ap[(r + 4) * K1_LDA + m + 8];
            }
            #pragma unroll
            for (int fn = 0; fn < 8; fn++) {
                const int n = wn * 64 + fn * 8 + g;
                const uint32_t b0 = bp[r * K1_LDB + n], b1 = bp[(r + 4) * K1_LDB + n];
                mma16(acc[0][fn], afr[0], b0, b1);
                mma16(acc[1][fn], afr[1], b0, b1);
            }
        }
        if (kt < 31) { stA(p ^ 1); cp_wait0(); }
        __syncthreads();
    }

    // epilogue: bias+relu -> fp32 g_h + bf16 g_hb4 in [kp][m] block layout
    uint32_t* hbw = (uint32_t*)g_hb4 + (size_t)blockIdx.x * 16384;
    #pragma unroll
    for (int fm = 0; fm < 2; fm++) {
        #pragma unroll
        for (int half = 0; half < 2; half++) {
            const int mloc = wm * 32 + fm * 16 + g + half * 8;
            const size_t m = mBase + mloc;
            #pragma unroll
            for (int fn = 0; fn < 8; fn++) {
                const int c = wn * 64 + fn * 8 + tg * 2;
                const float v0 = half ? acc[fm][fn].z : acc[fm][fn].x;
                const float v1 = half ? acc[fm][fn].w : acc[fm][fn].y;
                const float h0 = fmaxf(v0 + bias[c], 0.f);
                const float h1 = fmaxf(v1 + bias[c + 1], 0.f);
                *(float2*)&g_h[m * HH + c] = make_float2(h0, h1);
                hbw[(c >> 1) * 128 + mloc] = pbf(h0, h1);
            }
        }
    }
}

// ============================================================================
// K2: gated-attention logits. CTA 128 tokens, 256 thr, 2 CTAs/SM.
// 16 flattened stages (nb 0..3 x kh 0..3); A+B staged via pure cp.async,
// double-buffered, 2 barriers/stage. Fragment indexing identical to R6.
// ============================================================================
#define K2_LDA 136
#define K2_LDB 72
#define K2_AW  (32 * K2_LDA)    // 4352 words
#define K2_BW  (32 * K2_LDB)    // 2304 words
#define K2_SMEM ((2 * K2_AW + 4 * K2_BW) * 4)   // 71680 B
__global__ __launch_bounds__(256, 2)
void k2_gates(const float* __restrict__ bv, const float* __restrict__ bu,
              const float* __restrict__ ww, const float* __restrict__ bw,
              const unsigned char* __restrict__ mask)
{
    extern __shared__ uint32_t sm2[];
    uint32_t* As  = sm2;                  // [2][32][136]
    uint32_t* BVs = sm2 + 2 * K2_AW;      // [2][32][72]
    uint32_t* BUs = BVs + 2 * K2_BW;
    __shared__ float red[2][128];
    const uint32_t sA = s2u(As), sBV = s2u(BVs), sBU = s2u(BUs);

    const int tid = threadIdx.x;
    const int lane = tid & 31, wid = tid >> 5;
    const int wm = wid & 3, wn = wid >> 2;       // warp: rows wm*32, cols wn*32
    const int g = lane >> 2, tg = lane & 3;
    const size_t m0 = (size_t)blockIdx.x * 128;
    const char* aImg = (const char*)g_hb4 + (size_t)blockIdx.x * 65536;

    auto fill = [&](int s, int p) {
        const int kh = s & 3;
        #pragma unroll
        for (int j = 0; j < 4; j++) {              // A: 1024 chunks
            const int c = tid * 4 + j;
            const int row = c >> 5, col = c & 31;
            cpa16(sA + p * (K2_AW * 4) + row * (K2_LDA * 4) + col * 16,
                  aImg + (size_t)kh * 16384 + (size_t)c * 16);
        }
        #pragma unroll
        for (int j = 0; j < 2; j++) {              // B: 512 chunks each
            const int c = tid * 2 + j;
            const int row = c >> 4, col = c & 15;
            const uint32_t d = p * (K2_BW * 4) + row * (K2_LDB * 4) + col * 16;
            cpa16(sBV + d, (const char*)g_wvs + (size_t)s * 8192 + (size_t)c * 16);
            cpa16(sBU + d, (const char*)g_wus + (size_t)s * 8192 + (size_t)c * 16);
        }
    };

    fill(0, 0); cp_commit();

    float rowsum[4] = {0.f, 0.f, 0.f, 0.f};
    float4 accV[2][4], accU[2][4];

    for (int s = 0; s < 16; s++) {
        const int p = s & 1, nb = s >> 2, kh = s & 3;
        if (s < 15) { fill(s + 1, p ^ 1); cp_commit(); cp_wait1(); }
        else cp_wait0();
        __syncthreads();                  // stage s visible to all

        if (kh == 0) {
            #pragma unroll
            for (int i = 0; i < 2; i++)
                #pragma unroll
                for (int j = 0; j < 4; j++) {
                    accV[i][j] = make_float4(0.f, 0.f, 0.f, 0.f);
                    accU[i][j] = make_float4(0.f, 0.f, 0.f, 0.f);
                }
        }

        const uint32_t* ap = As  + p * K2_AW;
        const uint32_t* vp = BVs + p * K2_BW;
        const uint32_t* up = BUs + p * K2_BW;
        #pragma unroll
        for (int ks = 0; ks < 4; ks++) {
            const int r = ks * 8 + tg;
            uint32_t afr[2][4];
            #pragma unroll
            for (int fm = 0; fm < 2; fm++) {
                const int m = wm * 32 + fm * 16 + g;
                afr[fm][0] = ap[r * K2_LDA + m];       afr[fm][1] = ap[r * K2_LDA + m + 8];
                afr[fm][2] = ap[(r + 4) * K2_LDA + m]; afr[fm][3] = ap[(r + 4) * K2_LDA + m + 8];
            }
            #pragma unroll
            for (int fn = 0; fn < 4; fn++) {
                const int n = wn * 32 + fn * 8 + g;
                const uint32_t v0 = vp[r * K2_LDB + n], v1 = vp[(r + 4) * K2_LDB + n];
                const uint32_t u0 = up[r * K2_LDB + n], u1 = up[(r + 4) * K2_LDB + n];
                mma16(accV[0][fn], afr[0], v0, v1);
                mma16(accV[1][fn], afr[1], v0, v1);
                mma16(accU[0][fn], afr[0], u0, u1);
                mma16(accU[1][fn], afr[1], u0, u1);
            }
        }

        if (kh == 3) {
            #pragma unroll
            for (int fm = 0; fm < 2; fm++) {
                #pragma unroll
                for (int fn = 0; fn < 4; fn++) {
                    const int c = nb * 64 + wn * 32 + fn * 8 + tg * 2;
                    const float bv0 = bv[c], bv1 = bv[c + 1];
                    const float bu0 = bu[c], bu1 = bu[c + 1];
                    const float w0 = ww[c],  w1 = ww[c + 1];
                    const float4 av = accV[fm][fn], au = accU[fm][fn];
                    float v, u;
                    v = tanhfast(av.x + bv0); u = 0.5f * tanhfast(0.5f * (au.x + bu0)) + 0.5f;
                    rowsum[fm * 2 + 0] = fmaf(v * u, w0, rowsum[fm * 2 + 0]);
                    v = tanhfast(av.y + bv1); u = 0.5f * tanhfast(0.5f * (au.y + bu1)) + 0.5f;
                    rowsum[fm * 2 + 0] = fmaf(v * u, w1, rowsum[fm * 2 + 0]);
                    v = tanhfast(av.z + bv0); u = 0.5f * tanhfast(0.5f * (au.z + bu0)) + 0.5f;
                    rowsum[fm * 2 + 1] = fmaf(v * u, w0, rowsum[fm * 2 + 1]);
                    v = tanhfast(av.w + bv1); u = 0.5f * tanhfast(0.5f * (au.w + bu1)) + 0.5f;
                    rowsum[fm * 2 + 1] = fmaf(v * u, w1, rowsum[fm * 2 + 1]);
                }
            }
        }
        __syncthreads();                  // readers of stage p done before refill
    }

    #pragma unroll
    for (int o = 1; o <= 2; o <<= 1)
        #pragma unroll
        for (int i = 0; i < 4; i++)
            rowsum[i] += __shfl_xor_sync(0xffffffffu, rowsum[i], o);

    if (tg == 0) {
        #pragma unroll
        for (int i = 0; i < 4; i++)
            red[wn][wm * 32 + (i >> 1) * 16 + (i & 1) * 8 + g] = rowsum[i];
    }
    __syncthreads();
    if (tid < 128) {
        const size_t m = m0 + tid;
        float val = red[0][tid] + red[1][tid] + bw[0];
        if (mask[m]) val = -1e30f;
        g_logit[m] = val;
    }
}

// ============================================================================
// K3a/b/c + K4 (unchanged)
// ============================================================================
__global__ __launch_bounds__(1024)
void k3a_stats()
{
    __shared__ float sred[1024];
    const int b = blockIdx.x, tid = threadIdx.x;
    const float* lg = g_logit + (size_t)b * TT;

    float lmax = -FLT_MAX;
    #pragma unroll
    for (int i = 0; i < 8; i++) lmax = fmaxf(lmax, lg[tid + i * 1024]);
    sred[tid] = lmax;
    __syncthreads();
    for (int s = 512; s > 0; s >>= 1) {
        if (tid < s) sred[tid] = fmaxf(sred[tid], sred[tid + s]);
        __syncthreads();
    }
    const float mx = sred[0];
    __syncthreads();

    float lsum = 0.f;
    #pragma unroll
    for (int i = 0; i < 8; i++) lsum += __expf(lg[tid + i * 1024] - mx);
    sred[tid] = lsum;
    __syncthreads();
    for (int s = 512; s > 0; s >>= 1) {
        if (tid < s) sred[tid] += sred[tid + s];
        __syncthreads();
    }
    if (tid == 0) g_stat[b] = make_float2(mx, 1.f / sred[0]);
}

__global__ __launch_bounds__(256)
void k3b_pool()
{
    __shared__ float w[128];
    const int b = blockIdx.y, ch = blockIdx.x, tid = threadIdx.x;
    const float2 st = g_stat[b];
    const int t0 = ch * 128;

    if (tid < 128)
        w[tid] = __expf(g_logit[(size_t)b * TT + t0 + tid] - st.x) * st.y;
    __syncthreads();

    const float* hp = &g_h[((size_t)b * TT + t0) * HH + tid];
    float a0 = 0.f, a1 = 0.f, a2 = 0.f, a3 = 0.f;
    #pragma unroll 4
    for (int t = 0; t < 128; t += 4) {
        a0 = fmaf(w[t + 0], hp[(size_t)(t + 0) * HH], a0);
        a1 = fmaf(w[t + 1], hp[(size_t)(t + 1) * HH], a1);
        a2 = fmaf(w[t + 2], hp[(size_t)(t + 2) * HH], a2);
        a3 = fmaf(w[t + 3], hp[(size_t)(t + 3) * HH], a3);
    }
    g_part[((size_t)b * NCHUNK + ch) * HH + tid] = (a0 + a1) + (a2 + a3);
}

__global__ __launch_bounds__(256)
void k3c_reduce()
{
    const int b = blockIdx.x, c = threadIdx.x;
    float s = 0.f;
    #pragma unroll 8
    for (int j = 0; j < NCHUNK; j++) s += g_part[((size_t)b * NCHUNK + j) * HH + c];
    g_slide[b * HH + c] = s;
}

__global__ __launch_bounds__(512)
void k4_final(const float* __restrict__ Wc, const float* __restrict__ bc,
              float* __restrict__ out)
{
    const int tid = threadIdx.x;
    const int pair = tid >> 5, lane = tid & 31;
    const int b = pair >> 1, o = pair & 1;
    float s = 0.f;
    for (int j = lane; j < HH; j += 32)
        s = fmaf(g_slide[b * HH + j], Wc[j * OO + o], s);
    #pragma unroll
    for (int off = 16; off > 0; off >>= 1) s += __shfl_down_sync(0xffffffffu, s, off);
    if (lane == 0) out[b * OO + o] = s + bc[o];
}

// ============================================================================
extern "C" void kernel_launch(void* const* d_in, const int* in_sizes, int n_in,
                              void* d_out, int out_size)
{
    const float*         bags = (const float*)d_in[0];
    const unsigned char* mask = (const unsigned char*)d_in[1];
    const float*         W1   = (const float*)d_in[2];
    const float*         b1   = (const float*)d_in[3];
    const float*         Wv   = (const float*)d_in[4];
    const float*         bv   = (const float*)d_in[5];
    const float*         Wu   = (const float*)d_in[6];
    const float*         bu   = (const float*)d_in[7];
    const float*         ww   = (const float*)d_in[8];
    const float*         bw   = (const float*)d_in[9];
    const float*         Wc   = (const float*)d_in[10];
    const float*         bc   = (const float*)d_in[11];
    float*               out  = (float*)d_out;

    cudaFuncSetAttribute(k1_gemm_relu, cudaFuncAttributeMaxDynamicSharedMemorySize, K1_SMEM);
    cudaFuncSetAttribute(k2_gates,     cudaFuncAttributeMaxDynamicSharedMemorySize, K2_SMEM);

    k1pre<<<32, 256>>>(W1);
    k2pre<<<16, 256>>>(Wv, Wu);
    k1_gemm_relu<<<MTOK / 128, 512, K1_SMEM>>>(bags, b1);
    k2_gates<<<MTOK / 128, 256, K2_SMEM>>>(bv, bu, ww, bw, mask);
    k3a_stats<<<BSZ, 1024>>>();
    k3b_pool<<<dim3(NCHUNK, BSZ), 256>>>();
    k3c_reduce<<<BSZ, 256>>>();
    k4_final<<<1, 512>>>(Wc, bc, out);
}

// round 9
// speedup vs baseline: 1.1140x; 1.1140x over previous
#include <cuda_runtime.h>
#include <math.h>
#include <stdint.h>
#include <float.h>

#define BSZ 8
#define TT  8192
#define FF  1024
#define HH  256
#define OO  2
#define MTOK (BSZ * TT)   // 65536 tokens
#define NCHUNK 64

// ---- scratch (static device globals; no runtime allocation) ----
__device__ float  g_h[(size_t)MTOK * HH];     // 64 MB fp32 h (K3 pooling)
__device__ uint4  g_hb4[(size_t)MTOK * 32];   // 32 MB bf16 h, layout [mblk 512][kp 128][m 128]
__device__ float  g_logit[MTOK];
__device__ float2 g_stat[BSZ];
__device__ float  g_part[BSZ * NCHUNK * HH];
__device__ float  g_slide[BSZ * HH];
__device__ uint4  g_w1s[64 * 512];            // 512 KB: W1 bf16 [kt 64][kp 8][n 256] (R6 layout)
__device__ uint4  g_wvs[16 * 512];            // 128 KB: Wv bf16 [blk 16][kp 32][n 64]
__device__ uint4  g_wus[16 * 512];            // 128 KB: Wu

// ---- helpers ----
__device__ __forceinline__ uint32_t pbf(float lo, float hi) {
    uint32_t r; asm("cvt.rn.bf16x2.f32 %0, %1, %2;" : "=r"(r) : "f"(hi), "f"(lo)); return r;
}
__device__ __forceinline__ float tanhfast(float x) {
    float y; asm("tanh.approx.f32 %0, %1;" : "=f"(y) : "f"(x)); return y;
}
__device__ __forceinline__ void mma16(float4& d, const uint32_t* a, uint32_t b0, uint32_t b1) {
    asm volatile("mma.sync.aligned.m16n8k16.row.col.f32.bf16.bf16.f32 "
        "{%0,%1,%2,%3}, {%4,%5,%6,%7}, {%8,%9}, {%0,%1,%2,%3};"
        : "+f"(d.x), "+f"(d.y), "+f"(d.z), "+f"(d.w)
        : "r"(a[0]), "r"(a[1]), "r"(a[2]), "r"(a[3]), "r"(b0), "r"(b1));
}
__device__ __forceinline__ uint32_t s2u(const void* p) {
    uint32_t a; asm("{ .reg .u64 t; cvta.to.shared.u64 t, %1; cvt.u32.u64 %0, t; }" : "=r"(a) : "l"(p));
    return a;
}
__device__ __forceinline__ void cpa16(uint32_t dst, const void* src) {
    asm volatile("cp.async.cg.shared.global [%0], [%1], 16;" :: "r"(dst), "l"(src));
}
__device__ __forceinline__ void cp_commit() { asm volatile("cp.async.commit_group;"); }
__device__ __forceinline__ void cp_wait0()  { asm volatile("cp.async.wait_group 0;"); }
__device__ __forceinline__ void cp_wait1()  { asm volatile("cp.async.wait_group 1;"); }

// ============================================================================
// k1pre (R6 layout): W1 -> bf16 images [kt 64][kp 8][n 256].
// ============================================================================
__global__ __launch_bounds__(256)
void k1pre(const float* __restrict__ W1)
{
    const int kt = blockIdx.x, tid = threadIdx.x;
    const int kp = tid >> 5, n8 = (tid & 31) << 3;
    const float* r0 = W1 + (size_t)(kt * 16 + 2 * kp) * HH + n8;
    const float4 a0 = *(const float4*)(r0),        a1 = *(const float4*)(r0 + 4);
    const float4 b0 = *(const float4*)(r0 + HH),   b1 = *(const float4*)(r0 + HH + 4);
    g_w1s[kt * 512 + kp * 64 + (n8 >> 2)] =
        make_uint4(pbf(a0.x, b0.x), pbf(a0.y, b0.y), pbf(a0.z, b0.z), pbf(a0.w, b0.w));
    g_w1s[kt * 512 + kp * 64 + (n8 >> 2) + 1] =
        make_uint4(pbf(a1.x, b1.x), pbf(a1.y, b1.y), pbf(a1.z, b1.z), pbf(a1.w, b1.w));
}

// ============================================================================
// k2pre: Wv/Wu -> bf16 images [blk=nb*4+kh][kp 32][n 64].
// ============================================================================
__global__ __launch_bounds__(256)
void k2pre(const float* __restrict__ Wv, const float* __restrict__ Wu)
{
    const int blk = blockIdx.x, tid = threadIdx.x;
    const int nb = blk >> 2, kh = blk & 3;
    const int kp = tid >> 3, n8 = (tid & 7) << 3;
    const size_t off = (size_t)(kh * 64 + 2 * kp) * HH + nb * 64 + n8;
    {
        const float4 a0 = *(const float4*)(Wv + off),      a1 = *(const float4*)(Wv + off + 4);
        const float4 b0 = *(const float4*)(Wv + off + HH), b1 = *(const float4*)(Wv + off + HH + 4);
        g_wvs[blk * 512 + kp * 16 + (n8 >> 2)] =
            make_uint4(pbf(a0.x, b0.x), pbf(a0.y, b0.y), pbf(a0.z, b0.z), pbf(a0.w, b0.w));
        g_wvs[blk * 512 + kp * 16 + (n8 >> 2) + 1] =
            make_uint4(pbf(a1.x, b1.x), pbf(a1.y, b1.y), pbf(a1.z, b1.z), pbf(a1.w, b1.w));
    }
    {
        const float4 a0 = *(const float4*)(Wu + off),      a1 = *(const float4*)(Wu + off + 4);
        const float4 b0 = *(const float4*)(Wu + off + HH), b1 = *(const float4*)(Wu + off + HH + 4);
        g_wus[blk * 512 + kp * 16 + (n8 >> 2)] =
            make_uint4(pbf(a0.x, b0.x), pbf(a0.y, b0.y), pbf(a0.z, b0.z), pbf(a0.w, b0.w));
        g_wus[blk * 512 + kp * 16 + (n8 >> 2) + 1] =
            make_uint4(pbf(a1.x, b1.x), pbf(a1.y, b1.y), pbf(a1.z, b1.z), pbf(a1.w, b1.w));
    }
}

// ============================================================================
// K1 (R6 mainloop, proven at 320us): h = relu(bags @ W1 + b1).
// CTA 128x256, 512 thr, K=16 double-buffered, reg-prefetch A+B.
// Epilogue writes fp32 g_h + bf16 g_hb4 in [mblk][kp][m] layout.
// ============================================================================
#define LDA1 136
#define LDB1 264
__global__ __launch_bounds__(512, 1)
void k1_gemm_relu(const float* __restrict__ A, const float* __restrict__ bias)
{
    __shared__ uint32_t As[2][8][LDA1];   // [kpair][m]
    __shared__ uint32_t Bs[2][8][LDB1];   // [kpair][n]

    const int tid = threadIdx.x;
    const int lane = tid & 31, wid = tid >> 5;
    const int wm = wid & 3, wn = wid >> 2;       // warp: rows wm*32, cols wn*64
    const int g = lane >> 2, tg = lane & 3;
    const size_t mBase = (size_t)blockIdx.x * 128;

    const int am = tid >> 2, ak4 = (tid & 3) << 2;
    const int bkp = tid >> 6, bn4 = (tid & 63) << 2;
    const float* aP = A + (mBase + am) * FF + ak4;
    const uint4* bSrc = g_w1s + bkp * 64 + (bn4 >> 2);

    float4 acc[2][8];
    #pragma unroll
    for (int i = 0; i < 2; i++)
        #pragma unroll
        for (int j = 0; j < 8; j++) acc[i][j] = make_float4(0.f, 0.f, 0.f, 0.f);

    float4 ra;  uint4 rb;
    ra = *(const float4*)(aP);
    rb = bSrc[0];

    auto store_tile = [&](int p) {
        const int kp = ak4 >> 1;
        As[p][kp][am]     = pbf(ra.x, ra.y);
        As[p][kp + 1][am] = pbf(ra.z, ra.w);
        *(uint4*)&Bs[p][bkp][bn4] = rb;
    };

    store_tile(0);
    __syncthreads();

    for (int kt = 0; kt < 64; kt++) {
        const int p = kt & 1;
        if (kt + 1 < 64) {
            ra = *(const float4*)(aP + (kt + 1) * 16);
            rb = bSrc[(kt + 1) * 512];
        }
        uint32_t afr[2][4];
        #pragma unroll
        for (int fm = 0; fm < 2; fm++) {
            const int m = wm * 32 + fm * 16 + g;
            afr[fm][0] = As[p][tg][m];     afr[fm][1] = As[p][tg][m + 8];
            afr[fm][2] = As[p][tg + 4][m]; afr[fm][3] = As[p][tg + 4][m + 8];
        }
        #pragma unroll
        for (int fn = 0; fn < 8; fn++) {
            const int n = wn * 64 + fn * 8 + g;
            const uint32_t b0 = Bs[p][tg][n], b1 = Bs[p][tg + 4][n];
            mma16(acc[0][fn], afr[0], b0, b1);
            mma16(acc[1][fn], afr[1], b0, b1);
        }
        if (kt + 1 < 64) {
            store_tile(p ^ 1);
            __syncthreads();
        }
    }

    // epilogue: bias+relu -> fp32 g_h + bf16 g_hb4 ([mblk][kp 128][m 128])
    uint32_t* hbw = (uint32_t*)g_hb4 + (size_t)blockIdx.x * 16384;
    #pragma unroll
    for (int fm = 0; fm < 2; fm++) {
        #pragma unroll
        for (int half = 0; half < 2; half++) {
            const int mloc = wm * 32 + fm * 16 + g + half * 8;
            const size_t m = mBase + mloc;
            #pragma unroll
            for (int fn = 0; fn < 8; fn++) {
                const int c = wn * 64 + fn * 8 + tg * 2;
                const float v0 = half ? acc[fm][fn].z : acc[fm][fn].x;
                const float v1 = half ? acc[fm][fn].w : acc[fm][fn].y;
                const float h0 = fmaxf(v0 + bias[c], 0.f);
                const float h1 = fmaxf(v1 + bias[c + 1], 0.f);
                *(float2*)&g_h[m * HH + c] = make_float2(h0, h1);
                hbw[(c >> 1) * 128 + mloc] = pbf(h0, h1);
            }
        }
    }
}

// ============================================================================
// K2: gated-attention logits. CTA = 256 tokens, 512 thr (16 warps), 1 CTA/SM.
// A (256x256 bf16, 132 KB) resident in smem — cp.async-filled once.
// B double-buffered per stage s = nb*4+kh. Fragment indexing as R6.
// ============================================================================
#define K2_LDA 264
#define K2_AW  (128 * K2_LDA)   // 33792 words (132 KB)
#define K2_BW  (32 * 72)        // 2304 words per stage
#define K2_SMEM ((K2_AW + 4 * K2_BW) * 4)   // 172032 B
__global__ __launch_bounds__(512, 1)
void k2_gates(const float* __restrict__ bv, const float* __restrict__ bu,
              const float* __restrict__ ww, const float* __restrict__ bw,
              const unsigned char* __restrict__ mask)
{
    extern __shared__ uint32_t sm2[];
    uint32_t* As  = sm2;                  // [128 kp][264]
    uint32_t* BVs = sm2 + K2_AW;          // [2][32][72]
    uint32_t* BUs = BVs + 2 * K2_BW;
    __shared__ float red[2][256];
    const uint32_t sA = s2u(As), sBV = s2u(BVs), sBU = s2u(BUs);

    const int tid = threadIdx.x;
    const int lane = tid & 31, wid = tid >> 5;
    const int wm = wid & 7, wn = wid >> 3;       // warp: rows wm*32, cols wn*32
    const int g = lane >> 2, tg = lane & 3;
    const size_t m0 = (size_t)blockIdx.x * 256;
    const char* aImg = (const char*)g_hb4 + (size_t)(2 * blockIdx.x) * 65536;

    auto fillB = [&](int s, int p) {
        const int c = tid;                        // 512 chunks per matrix
        const int row = c >> 4, col = c & 15;
        const uint32_t d = p * (K2_BW * 4) + row * (72 * 4) + col * 16;
        cpa16(sBV + d, (const char*)g_wvs + (size_t)s * 8192 + (size_t)c * 16);
        cpa16(sBU + d, (const char*)g_wus + (size_t)s * 8192 + (size_t)c * 16);
    };

    // ---- A fill: 8192 16B-chunks (two m-blocks), 16 per thread ----
    #pragma unroll
    for (int j = 0; j < 16; j++) {
        const int c = j * 512 + tid;
        const int q = c >> 12, r = c & 4095;
        const int kp = r >> 5, mw = (r & 31) << 2;
        cpa16(sA + (kp * K2_LDA + q * 128 + mw) * 4, aImg + (size_t)c * 16);
    }
    fillB(0, 0);
    cp_commit();

    float rowsum[4] = {0.f, 0.f, 0.f, 0.f};
    float4 accV[2][4], accU[2][4];

    for (int s = 0; s < 16; s++) {
        const int p = s & 1, nb = s >> 2, kh = s & 3;
        if (s < 15) { fillB(s + 1, p ^ 1); cp_commit(); cp_wait1(); }
        else cp_wait0();
        __syncthreads();                  // stage s (and A on s==0) visible

        if (kh == 0) {
            #pragma unroll
            for (int i = 0; i < 2; i++)
                #pragma unroll
                for (int j = 0; j < 4; j++) {
                    accV[i][j] = make_float4(0.f, 0.f, 0.f, 0.f);
                    accU[i][j] = make_float4(0.f, 0.f, 0.f, 0.f);
                }
        }

        const uint32_t* vp = BVs + p * K2_BW;
        const uint32_t* up = BUs + p * K2_BW;
        #pragma unroll
        for (int ks = 0; ks < 4; ks++) {
            const int r = ks * 8 + tg;
            const int ra = kh * 32 + r;
            uint32_t afr[2][4];
            #pragma unroll
            for (int fm = 0; fm < 2; fm++) {
                const int m = wm * 32 + fm * 16 + g;
                afr[fm][0] = As[ra * K2_LDA + m];       afr[fm][1] = As[ra * K2_LDA + m + 8];
                afr[fm][2] = As[(ra + 4) * K2_LDA + m]; afr[fm][3] = As[(ra + 4) * K2_LDA + m + 8];
            }
            #pragma unroll
            for (int fn = 0; fn < 4; fn++) {
                const int n = wn * 32 + fn * 8 + g;
                const uint32_t v0 = vp[r * 72 + n], v1 = vp[(r + 4) * 72 + n];
                const uint32_t u0 = up[r * 72 + n], u1 = up[(r + 4) * 72 + n];
                mma16(accV[0][fn], afr[0], v0, v1);
                mma16(accV[1][fn], afr[1], v0, v1);
                mma16(accU[0][fn], afr[0], u0, u1);
                mma16(accU[1][fn], afr[1], u0, u1);
            }
        }

        if (kh == 3) {
            #pragma unroll
            for (int fm = 0; fm < 2; fm++) {
                #pragma unroll
                for (int fn = 0; fn < 4; fn++) {
                    const int c = nb * 64 + wn * 32 + fn * 8 + tg * 2;
                    const float bv0 = bv[c], bv1 = bv[c + 1];
                    const float bu0 = bu[c], bu1 = bu[c + 1];
                    const float w0 = ww[c],  w1 = ww[c + 1];
                    const float4 av = accV[fm][fn], au = accU[fm][fn];
                    float v, u;
                    v = tanhfast(av.x + bv0); u = 0.5f * tanhfast(0.5f * (au.x + bu0)) + 0.5f;
                    rowsum[fm * 2 + 0] = fmaf(v * u, w0, rowsum[fm * 2 + 0]);
                    v = tanhfast(av.y + bv1); u = 0.5f * tanhfast(0.5f * (au.y + bu1)) + 0.5f;
                    rowsum[fm * 2 + 0] = fmaf(v * u, w1, rowsum[fm * 2 + 0]);
                    v = tanhfast(av.z + bv0); u = 0.5f * tanhfast(0.5f * (au.z + bu0)) + 0.5f;
                    rowsum[fm * 2 + 1] = fmaf(v * u, w0, rowsum[fm * 2 + 1]);
                    v = tanhfast(av.w + bv1); u = 0.5f * tanhfast(0.5f * (au.w + bu1)) + 0.5f;
                    rowsum[fm * 2 + 1] = fmaf(v * u, w1, rowsum[fm * 2 + 1]);
                }
            }
        }
        __syncthreads();                  // readers of stage p done before refill
    }

    #pragma unroll
    for (int o = 1; o <= 2; o <<= 1)
        #pragma unroll
        for (int i = 0; i < 4; i++)
            rowsum[i] += __shfl_xor_sync(0xffffffffu, rowsum[i], o);

    if (tg == 0) {
        #pragma unroll
        for (int i = 0; i < 4; i++)
            red[wn][wm * 32 + (i >> 1) * 16 + (i & 1) * 8 + g] = rowsum[i];
    }
    __syncthreads();
    if (tid < 256) {
        const size_t m = m0 + tid;
        float val = red[0][tid] + red[1][tid] + bw[0];
        if (mask[m]) val = -1e30f;
        g_logit[m] = val;
    }
}

// ============================================================================
// K3a/b/c + K4 (unchanged)
// ============================================================================
__global__ __launch_bounds__(1024)
void k3a_stats()
{
    __shared__ float sred[1024];
    const int b = blockIdx.x, tid = threadIdx.x;
    const float* lg = g_logit + (size_t)b * TT;

    float lmax = -FLT_MAX;
    #pragma unroll
    for (int i = 0; i < 8; i++) lmax = fmaxf(lmax, lg[tid + i * 1024]);
    sred[tid] = lmax;
    __syncthreads();
    for (int s = 512; s > 0; s >>= 1) {
        if (tid < s) sred[tid] = fmaxf(sred[tid], sred[tid + s]);
        __syncthreads();
    }
    const float mx = sred[0];
    __syncthreads();

    float lsum = 0.f;
    #pragma unroll
    for (int i = 0; i < 8; i++) lsum += __expf(lg[tid + i * 1024] - mx);
    sred[tid] = lsum;
    __syncthreads();
    for (int s = 512; s > 0; s >>= 1) {
        if (tid < s) sred[tid] += sred[tid + s];
        __syncthreads();
    }
    if (tid == 0) g_stat[b] = make_float2(mx, 1.f / sred[0]);
}

__global__ __launch_bounds__(256)
void k3b_pool()
{
    __shared__ float w[128];
    const int b = blockIdx.y, ch = blockIdx.x, tid = threadIdx.x;
    const float2 st = g_stat[b];
    const int t0 = ch * 128;

    if (tid < 128)
        w[tid] = __expf(g_logit[(size_t)b * TT + t0 + tid] - st.x) * st.y;
    __syncthreads();

    const float* hp = &g_h[((size_t)b * TT + t0) * HH + tid];
    float a0 = 0.f, a1 = 0.f, a2 = 0.f, a3 = 0.f;
    #pragma unroll 4
    for (int t = 0; t < 128; t += 4) {
        a0 = fmaf(w[t + 0], hp[(size_t)(t + 0) * HH], a0);
        a1 = fmaf(w[t + 1], hp[(size_t)(t + 1) * HH], a1);
        a2 = fmaf(w[t + 2], hp[(size_t)(t + 2) * HH], a2);
        a3 = fmaf(w[t + 3], hp[(size_t)(t + 3) * HH], a3);
    }
    g_part[((size_t)b * NCHUNK + ch) * HH + tid] = (a0 + a1) + (a2 + a3);
}

__global__ __launch_bounds__(256)
void k3c_reduce()
{
    const int b = blockIdx.x, c = threadIdx.x;
    float s = 0.f;
    #pragma unroll 8
    for (int j = 0; j < NCHUNK; j++) s += g_part[((size_t)b * NCHUNK + j) * HH + c];
    g_slide[b * HH + c] = s;
}

__global__ __launch_bounds__(512)
void k4_final(const float* __restrict__ Wc, const float* __restrict__ bc,
              float* __restrict__ out)
{
    const int tid = threadIdx.x;
    const int pair = tid >> 5, lane = tid & 31;
    const int b = pair >> 1, o = pair & 1;
    float s = 0.f;
    for (int j = lane; j < HH; j += 32)
        s = fmaf(g_slide[b * HH + j], Wc[j * OO + o], s);
    #pragma unroll
    for (int off = 16; off > 0; off >>= 1) s += __shfl_down_sync(0xffffffffu, s, off);
    if (lane == 0) out[b * OO + o] = s + bc[o];
}

// ============================================================================
extern "C" void kernel_launch(void* const* d_in, const int* in_sizes, int n_in,
                              void* d_out, int out_size)
{
    const float*         bags = (const float*)d_in[0];
    const unsigned char* mask = (const unsigned char*)d_in[1];
    const float*         W1   = (const float*)d_in[2];
    const float*         b1   = (const float*)d_in[3];
    const float*         Wv   = (const float*)d_in[4];
    const float*         bv   = (const float*)d_in[5];
    const float*         Wu   = (const float*)d_in[6];
    const float*         bu   = (const float*)d_in[7];
    const float*         ww   = (const float*)d_in[8];
    const float*         bw   = (const float*)d_in[9];
    const float*         Wc   = (const float*)d_in[10];
    const float*         bc   = (const float*)d_in[11];
    float*               out  = (float*)d_out;

    cudaFuncSetAttribute(k2_gates, cudaFuncAttributeMaxDynamicSharedMemorySize, K2_SMEM);

    k1pre<<<64, 256>>>(W1);
    k2pre<<<16, 256>>>(Wv, Wu);
    k1_gemm_relu<<<MTOK / 128, 512>>>(bags, b1);
    k2_gates<<<MTOK / 256, 512, K2_SMEM>>>(bv, bu, ww, bw, mask);
    k3a_stats<<<BSZ, 1024>>>();
    k3b_pool<<<dim3(NCHUNK, BSZ), 256>>>();
    k3c_reduce<<<BSZ, 256>>>();
    k4_final<<<1, 512>>>(Wc, bc, out);
}

// round 10
// speedup vs baseline: 1.1758x; 1.0554x over previous
#include <cuda_runtime.h>
#include <math.h>
#include <stdint.h>
#include <float.h>

#define BSZ 8
#define TT  8192
#define FF  1024
#define HH  256
#define OO  2
#define MTOK (BSZ * TT)   // 65536 tokens
#define NCHUNK 64

// ---- scratch (static device globals; no runtime allocation) ----
__device__ float  g_h[(size_t)MTOK * HH];     // 64 MB fp32 h (K3 pooling)
__device__ uint4  g_hb4[(size_t)MTOK * 32];   // 32 MB bf16 h, layout [mblk 512][kp 128][m 128]
__device__ float  g_logit[MTOK];
__device__ float2 g_stat[BSZ];
__device__ float  g_part[BSZ * NCHUNK * HH];
__device__ float  g_slide[BSZ * HH];
__device__ uint4  g_w1s[64 * 512];            // 512 KB: W1 bf16 [kt 64][kp 8][n 256]
__device__ uint4  g_wvs[16 * 512];            // 128 KB: Wv bf16 [blk 16][kp 32][n 64]
__device__ uint4  g_wus[16 * 512];            // 128 KB: Wu

// ---- helpers ----
__device__ __forceinline__ uint32_t pbf(float lo, float hi) {
    uint32_t r; asm("cvt.rn.bf16x2.f32 %0, %1, %2;" : "=r"(r) : "f"(hi), "f"(lo)); return r;
}
__device__ __forceinline__ float tanhfast(float x) {
    float y; asm("tanh.approx.f32 %0, %1;" : "=f"(y) : "f"(x)); return y;
}
__device__ __forceinline__ void mma16(float4& d, const uint32_t* a, uint32_t b0, uint32_t b1) {
    asm volatile("mma.sync.aligned.m16n8k16.row.col.f32.bf16.bf16.f32 "
        "{%0,%1,%2,%3}, {%4,%5,%6,%7}, {%8,%9}, {%0,%1,%2,%3};"
        : "+f"(d.x), "+f"(d.y), "+f"(d.z), "+f"(d.w)
        : "r"(a[0]), "r"(a[1]), "r"(a[2]), "r"(a[3]), "r"(b0), "r"(b1));
}
__device__ __forceinline__ uint32_t s2u(const void* p) {
    uint32_t a; asm("{ .reg .u64 t; cvta.to.shared.u64 t, %1; cvt.u32.u64 %0, t; }" : "=r"(a) : "l"(p));
    return a;
}
__device__ __forceinline__ void cpa16(uint32_t dst, const void* src) {
    asm volatile("cp.async.cg.shared.global [%0], [%1], 16;" :: "r"(dst), "l"(src));
}
__device__ __forceinline__ void cp_commit() { asm volatile("cp.async.commit_group;"); }
__device__ __forceinline__ void cp_wait0()  { asm volatile("cp.async.wait_group 0;"); }
__device__ __forceinline__ void cp_wait1()  { asm volatile("cp.async.wait_group 1;"); }
__device__ __forceinline__ void cp_wait2()  { asm volatile("cp.async.wait_group 2;"); }

// ============================================================================
// k1pre: W1 -> bf16 images [kt 64][kp 8][n 256].
// ============================================================================
__global__ __launch_bounds__(256)
void k1pre(const float* __restrict__ W1)
{
    const int kt = blockIdx.x, tid = threadIdx.x;
    const int kp = tid >> 5, n8 = (tid & 31) << 3;
    const float* r0 = W1 + (size_t)(kt * 16 + 2 * kp) * HH + n8;
    const float4 a0 = *(const float4*)(r0),        a1 = *(const float4*)(r0 + 4);
    const float4 b0 = *(const float4*)(r0 + HH),   b1 = *(const float4*)(r0 + HH + 4);
    g_w1s[kt * 512 + kp * 64 + (n8 >> 2)] =
        make_uint4(pbf(a0.x, b0.x), pbf(a0.y, b0.y), pbf(a0.z, b0.z), pbf(a0.w, b0.w));
    g_w1s[kt * 512 + kp * 64 + (n8 >> 2) + 1] =
        make_uint4(pbf(a1.x, b1.x), pbf(a1.y, b1.y), pbf(a1.z, b1.z), pbf(a1.w, b1.w));
}

// ============================================================================
// k2pre: Wv/Wu -> bf16 images [blk=nb*4+kh][kp 32][n 64].
// ============================================================================
__global__ __launch_bounds__(256)
void k2pre(const float* __restrict__ Wv, const float* __restrict__ Wu)
{
    const int blk = blockIdx.x, tid = threadIdx.x;
    const int nb = blk >> 2, kh = blk & 3;
    const int kp = tid >> 3, n8 = (tid & 7) << 3;
    const size_t off = (size_t)(kh * 64 + 2 * kp) * HH + nb * 64 + n8;
    {
        const float4 a0 = *(const float4*)(Wv + off),      a1 = *(const float4*)(Wv + off + 4);
        const float4 b0 = *(const float4*)(Wv + off + HH), b1 = *(const float4*)(Wv + off + HH + 4);
        g_wvs[blk * 512 + kp * 16 + (n8 >> 2)] =
            make_uint4(pbf(a0.x, b0.x), pbf(a0.y, b0.y), pbf(a0.z, b0.z), pbf(a0.w, b0.w));
        g_wvs[blk * 512 + kp * 16 + (n8 >> 2) + 1] =
            make_uint4(pbf(a1.x, b1.x), pbf(a1.y, b1.y), pbf(a1.z, b1.z), pbf(a1.w, b1.w));
    }
    {
        const float4 a0 = *(const float4*)(Wu + off),      a1 = *(const float4*)(Wu + off + 4);
        const float4 b0 = *(const float4*)(Wu + off + HH), b1 = *(const float4*)(Wu + off + HH + 4);
        g_wus[blk * 512 + kp * 16 + (n8 >> 2)] =
            make_uint4(pbf(a0.x, b0.x), pbf(a0.y, b0.y), pbf(a0.z, b0.z), pbf(a0.w, b0.w));
        g_wus[blk * 512 + kp * 16 + (n8 >> 2) + 1] =
            make_uint4(pbf(a1.x, b1.x), pbf(a1.y, b1.y), pbf(a1.z, b1.z), pbf(a1.w, b1.w));
    }
}

// ============================================================================
// K1: h = relu(bags @ W1 + b1). CTA 128x256, 512 thr.
// NEW: 4-stage cp.async pipeline. A staged raw fp32 (each thread converts the
// exact chunk it copied -> no wait/convert barrier), B cp.async direct from
// g_w1s. Fragment math + epilogue byte-identical to R9.
// ============================================================================
#define K1_ARW   20                 // words per raw A row (80 B: 64B data + pad)
#define K1_ASTG  (128 * K1_ARW)     // 2560 words / stage
#define K1_BSTG  (8 * 264)          // 2112 words / stage
#define K1_BFA   (8 * 136)          // 1088 words / buffer
#define K1_SMEM  ((4 * K1_ASTG + 4 * K1_BSTG + 2 * K1_BFA) * 4)   // 83456 B
__global__ __launch_bounds__(512, 1)
void k1_gemm_relu(const float* __restrict__ A, const float* __restrict__ bias)
{
    extern __shared__ uint32_t sm1[];
    uint32_t* Araw = sm1;                       // [4][128][20] raw fp32
    uint32_t* Bst  = sm1 + 4 * K1_ASTG;         // [4][8][264] bf16 pairs
    uint32_t* bfA  = Bst + 4 * K1_BSTG;         // [2][8][136] bf16 pairs
    const uint32_t sAraw = s2u(Araw), sBst = s2u(Bst);

    const int tid = threadIdx.x;
    const int lane = tid & 31, wid = tid >> 5;
    const int wm = wid & 3, wn = wid >> 2;       // warp: rows wm*32, cols wn*64
    const int g = lane >> 2, tg = lane & 3;
    const size_t mBase = (size_t)blockIdx.x * 128;

    // fill/convert mapping: thread t owns A chunk (row t>>2, quarter t&3)
    const int ar = tid >> 2, aq = tid & 3;
    const float* aSrc = A + (mBase + ar) * FF + aq * 4;
    const int bkp = tid >> 6, bn4 = (tid & 63) << 2;   // B chunk

    auto issue = [&](int kt) {
        const int slot = kt & 3;
        cpa16(sAraw + (slot * K1_ASTG + ar * K1_ARW + aq * 4) * 4, aSrc + kt * 16);
        cpa16(sBst + (slot * K1_BSTG + bkp * 264 + bn4) * 4,
              (const char*)g_w1s + (size_t)kt * 8192 + (size_t)tid * 16);
        cp_commit();
    };
    issue(0); issue(1); issue(2);

    float4 acc[2][8];
    #pragma unroll
    for (int i = 0; i < 2; i++)
        #pragma unroll
        for (int j = 0; j < 8; j++) acc[i][j] = make_float4(0.f, 0.f, 0.f, 0.f);

    for (int kt = 0; kt < 64; kt++) {
        if (kt <= 61) cp_wait2();
        else if (kt == 62) cp_wait1();
        else cp_wait0();

        // convert own raw chunk -> bf16 [kp][136] (no barrier needed: own data)
        {
            const uint32_t* rw = Araw + (kt & 3) * K1_ASTG + ar * K1_ARW + aq * 4;
            const float4 v = *(const float4*)rw;
            uint32_t* bf = bfA + (kt & 1) * K1_BFA;
            bf[(aq * 2 + 0) * 136 + ar] = pbf(v.x, v.y);
            bf[(aq * 2 + 1) * 136 + ar] = pbf(v.z, v.w);
        }
        __syncthreads();     // publish bf16 A + B stage; also drains slot (kt-1)%4
        if (kt + 3 < 64) issue(kt + 3);   // slot (kt+3)%4 == (kt-1)%4: safe post-barrier

        const uint32_t* ap = bfA + (kt & 1) * K1_BFA;
        const uint32_t* bp = Bst + (kt & 3) * K1_BSTG;
        uint32_t afr[2][4];
        #pragma unroll
        for (int fm = 0; fm < 2; fm++) {
            const int m = wm * 32 + fm * 16 + g;
            afr[fm][0] = ap[tg * 136 + m];       afr[fm][1] = ap[tg * 136 + m + 8];
            afr[fm][2] = ap[(tg + 4) * 136 + m]; afr[fm][3] = ap[(tg + 4) * 136 + m + 8];
        }
        #pragma unroll
        for (int fn = 0; fn < 8; fn++) {
            const int n = wn * 64 + fn * 8 + g;
            const uint32_t b0 = bp[tg * 264 + n], b1 = bp[(tg + 4) * 264 + n];
            mma16(acc[0][fn], afr[0], b0, b1);
            mma16(acc[1][fn], afr[1], b0, b1);
        }
    }
    __syncthreads();

    // epilogue (R9-identical): bias+relu -> fp32 g_h + bf16 g_hb4 [mblk][kp][m]
    uint32_t* hbw = (uint32_t*)g_hb4 + (size_t)blockIdx.x * 16384;
    #pragma unroll
    for (int fm = 0; fm < 2; fm++) {
        #pragma unroll
        for (int half = 0; half < 2; half++) {
            const int mloc = wm * 32 + fm * 16 + g + half * 8;
            const size_t m = mBase + mloc;
            #pragma unroll
            for (int fn = 0; fn < 8; fn++) {
                const int c = wn * 64 + fn * 8 + tg * 2;
                const float v0 = half ? acc[fm][fn].z : acc[fm][fn].x;
                const float v1 = half ? acc[fm][fn].w : acc[fm][fn].y;
                const float h0 = fmaxf(v0 + bias[c], 0.f);
                const float h1 = fmaxf(v1 + bias[c + 1], 0.f);
                *(float2*)&g_h[m * HH + c] = make_float2(h0, h1);
                hbw[(c >> 1) * 128 + mloc] = pbf(h0, h1);
            }
        }
    }
}

// ============================================================================
// K2 (R9-identical, 68us): CTA 256 tokens, 512 thr, A resident, B double-buf.
// ============================================================================
#define K2_LDA 264
#define K2_AW  (128 * K2_LDA)   // 33792 words (132 KB)
#define K2_BW  (32 * 72)        // 2304 words per stage
#define K2_SMEM ((K2_AW + 4 * K2_BW) * 4)   // 172032 B
__global__ __launch_bounds__(512, 1)
void k2_gates(const float* __restrict__ bv, const float* __restrict__ bu,
              const float* __restrict__ ww, const float* __restrict__ bw,
              const unsigned char* __restrict__ mask)
{
    extern __shared__ uint32_t sm2[];
    uint32_t* As  = sm2;                  // [128 kp][264]
    uint32_t* BVs = sm2 + K2_AW;          // [2][32][72]
    uint32_t* BUs = BVs + 2 * K2_BW;
    __shared__ float red[2][256];
    const uint32_t sA = s2u(As), sBV = s2u(BVs), sBU = s2u(BUs);

    const int tid = threadIdx.x;
    const int lane = tid & 31, wid = tid >> 5;
    const int wm = wid & 7, wn = wid >> 3;       // warp: rows wm*32, cols wn*32
    const int g = lane >> 2, tg = lane & 3;
    const size_t m0 = (size_t)blockIdx.x * 256;
    const char* aImg = (const char*)g_hb4 + (size_t)(2 * blockIdx.x) * 65536;

    auto fillB = [&](int s, int p) {
        const int c = tid;
        const int row = c >> 4, col = c & 15;
        const uint32_t d = p * (K2_BW * 4) + row * (72 * 4) + col * 16;
        cpa16(sBV + d, (const char*)g_wvs + (size_t)s * 8192 + (size_t)c * 16);
        cpa16(sBU + d, (const char*)g_wus + (size_t)s * 8192 + (size_t)c * 16);
    };

    #pragma unroll
    for (int j = 0; j < 16; j++) {
        const int c = j * 512 + tid;
        const int q = c >> 12, r = c & 4095;
        const int kp = r >> 5, mw = (r & 31) << 2;
        cpa16(sA + (kp * K2_LDA + q * 128 + mw) * 4, aImg + (size_t)c * 16);
    }
    fillB(0, 0);
    cp_commit();

    float rowsum[4] = {0.f, 0.f, 0.f, 0.f};
    float4 accV[2][4], accU[2][4];

    for (int s = 0; s < 16; s++) {
        const int p = s & 1, nb = s >> 2, kh = s & 3;
        if (s < 15) { fillB(s + 1, p ^ 1); cp_commit(); cp_wait1(); }
        else cp_wait0();
        __syncthreads();

        if (kh == 0) {
            #pragma unroll
            for (int i = 0; i < 2; i++)
                #pragma unroll
                for (int j = 0; j < 4; j++) {
                    accV[i][j] = make_float4(0.f, 0.f, 0.f, 0.f);
                    accU[i][j] = make_float4(0.f, 0.f, 0.f, 0.f);
                }
        }

        const uint32_t* vp = BVs + p * K2_BW;
        const uint32_t* up = BUs + p * K2_BW;
        #pragma unroll
        for (int ks = 0; ks < 4; ks++) {
            const int r = ks * 8 + tg;
            const int ra = kh * 32 + r;
            uint32_t afr[2][4];
            #pragma unroll
            for (int fm = 0; fm < 2; fm++) {
                const int m = wm * 32 + fm * 16 + g;
                afr[fm][0] = As[ra * K2_LDA + m];       afr[fm][1] = As[ra * K2_LDA + m + 8];
                afr[fm][2] = As[(ra + 4) * K2_LDA + m]; afr[fm][3] = As[(ra + 4) * K2_LDA + m + 8];
            }
            #pragma unroll
            for (int fn = 0; fn < 4; fn++) {
                const int n = wn * 32 + fn * 8 + g;
                const uint32_t v0 = vp[r * 72 + n], v1 = vp[(r + 4) * 72 + n];
                const uint32_t u0 = up[r * 72 + n], u1 = up[(r + 4) * 72 + n];
                mma16(accV[0][fn], afr[0], v0, v1);
                mma16(accV[1][fn], afr[1], v0, v1);
                mma16(accU[0][fn], afr[0], u0, u1);
                mma16(accU[1][fn], afr[1], u0, u1);
            }
        }

        if (kh == 3) {
            #pragma unroll
            for (int fm = 0; fm < 2; fm++) {
                #pragma unroll
                for (int fn = 0; fn < 4; fn++) {
                    const int c = nb * 64 + wn * 32 + fn * 8 + tg * 2;
                    const float bv0 = bv[c], bv1 = bv[c + 1];
                    const float bu0 = bu[c], bu1 = bu[c + 1];
                    const float w0 = ww[c],  w1 = ww[c + 1];
                    const float4 av = accV[fm][fn], au = accU[fm][fn];
                    float v, u;
                    v = tanhfast(av.x + bv0); u = 0.5f * tanhfast(0.5f * (au.x + bu0)) + 0.5f;
                    rowsum[fm * 2 + 0] = fmaf(v * u, w0, rowsum[fm * 2 + 0]);
                    v = tanhfast(av.y + bv1); u = 0.5f * tanhfast(0.5f * (au.y + bu1)) + 0.5f;
                    rowsum[fm * 2 + 0] = fmaf(v * u, w1, rowsum[fm * 2 + 0]);
                    v = tanhfast(av.z + bv0); u = 0.5f * tanhfast(0.5f * (au.z + bu0)) + 0.5f;
                    rowsum[fm * 2 + 1] = fmaf(v * u, w0, rowsum[fm * 2 + 1]);
                    v = tanhfast(av.w + bv1); u = 0.5f * tanhfast(0.5f * (au.w + bu1)) + 0.5f;
                    rowsum[fm * 2 + 1] = fmaf(v * u, w1, rowsum[fm * 2 + 1]);
                }
            }
        }
        __syncthreads();
    }

    #pragma unroll
    for (int o = 1; o <= 2; o <<= 1)
        #pragma unroll
        for (int i = 0; i < 4; i++)
            rowsum[i] += __shfl_xor_sync(0xffffffffu, rowsum[i], o);

    if (tg == 0) {
        #pragma unroll
        for (int i = 0; i < 4; i++)
            red[wn][wm * 32 + (i >> 1) * 16 + (i & 1) * 8 + g] = rowsum[i];
    }
    __syncthreads();
    if (tid < 256) {
        const size_t m = m0 + tid;
        float val = red[0][tid] + red[1][tid] + bw[0];
        if (mask[m]) val = -1e30f;
        g_logit[m] = val;
    }
}

// ============================================================================
// K3a/b/c + K4 (unchanged)
// ============================================================================
__global__ __launch_bounds__(1024)
void k3a_stats()
{
    __shared__ float sred[1024];
    const int b = blockIdx.x, tid = threadIdx.x;
    const float* lg = g_logit + (size_t)b * TT;

    float lmax = -FLT_MAX;
    #pragma unroll
    for (int i = 0; i < 8; i++) lmax = fmaxf(lmax, lg[tid + i * 1024]);
    sred[tid] = lmax;
    __syncthreads();
    for (int s = 512; s > 0; s >>= 1) {
        if (tid < s) sred[tid] = fmaxf(sred[tid], sred[tid + s]);
        __syncthreads();
    }
    const float mx = sred[0];
    __syncthreads();

    float lsum = 0.f;
    #pragma unroll
    for (int i = 0; i < 8; i++) lsum += __expf(lg[tid + i * 1024] - mx);
    sred[tid] = lsum;
    __syncthreads();
    for (int s = 512; s > 0; s >>= 1) {
        if (tid < s) sred[tid] += sred[tid + s];
        __syncthreads();
    }
    if (tid == 0) g_stat[b] = make_float2(mx, 1.f / sred[0]);
}

__global__ __launch_bounds__(256)
void k3b_pool()
{
    __shared__ float w[128];
    const int b = blockIdx.y, ch = blockIdx.x, tid = threadIdx.x;
    const float2 st = g_stat[b];
    const int t0 = ch * 128;

    if (tid < 128)
        w[tid] = __expf(g_logit[(size_t)b * TT + t0 + tid] - st.x) * st.y;
    __syncthreads();

    const float* hp = &g_h[((size_t)b * TT + t0) * HH + tid];
    float a0 = 0.f, a1 = 0.f, a2 = 0.f, a3 = 0.f;
    #pragma unroll 4
    for (int t = 0; t < 128; t += 4) {
        a0 = fmaf(w[t + 0], hp[(size_t)(t + 0) * HH], a0);
        a1 = fmaf(w[t + 1], hp[(size_t)(t + 1) * HH], a1);
        a2 = fmaf(w[t + 2], hp[(size_t)(t + 2) * HH], a2);
        a3 = fmaf(w[t + 3], hp[(size_t)(t + 3) * HH], a3);
    }
    g_part[((size_t)b * NCHUNK + ch) * HH + tid] = (a0 + a1) + (a2 + a3);
}

__global__ __launch_bounds__(256)
void k3c_reduce()
{
    const int b = blockIdx.x, c = threadIdx.x;
    float s = 0.f;
    #pragma unroll 8
    for (int j = 0; j < NCHUNK; j++) s += g_part[((size_t)b * NCHUNK + j) * HH + c];
    g_slide[b * HH + c] = s;
}

__global__ __launch_bounds__(512)
void k4_final(const float* __restrict__ Wc, const float* __restrict__ bc,
              float* __restrict__ out)
{
    const int tid = threadIdx.x;
    const int pair = tid >> 5, lane = tid & 31;
    const int b = pair >> 1, o = pair & 1;
    float s = 0.f;
    for (int j = lane; j < HH; j += 32)
        s = fmaf(g_slide[b * HH + j], Wc[j * OO + o], s);
    #pragma unroll
    for (int off = 16; off > 0; off >>= 1) s += __shfl_down_sync(0xffffffffu, s, off);
    if (lane == 0) out[b * OO + o] = s + bc[o];
}

// ============================================================================
extern "C" void kernel_launch(void* const* d_in, const int* in_sizes, int n_in,
                              void* d_out, int out_size)
{
    const float*         bags = (const float*)d_in[0];
    const unsigned char* mask = (const unsigned char*)d_in[1];
    const float*         W1   = (const float*)d_in[2];
    const float*         b1   = (const float*)d_in[3];
    const float*         Wv   = (const float*)d_in[4];
    const float*         bv   = (const float*)d_in[5];
    const float*         Wu   = (const float*)d_in[6];
    const float*         bu   = (const float*)d_in[7];
    const float*         ww   = (const float*)d_in[8];
    const float*         bw   = (const float*)d_in[9];
    const float*         Wc   = (const float*)d_in[10];
    const float*         bc   = (const float*)d_in[11];
    float*               out  = (float*)d_out;

    cudaFuncSetAttribute(k1_gemm_relu, cudaFuncAttributeMaxDynamicSharedMemorySize, K1_SMEM);
    cudaFuncSetAttribute(k2_gates,     cudaFuncAttributeMaxDynamicSharedMemorySize, K2_SMEM);

    k1pre<<<64, 256>>>(W1);
    k2pre<<<16, 256>>>(Wv, Wu);
    k1_gemm_relu<<<MTOK / 128, 512, K1_SMEM>>>(bags, b1);
    k2_gates<<<MTOK / 256, 512, K2_SMEM>>>(bv, bu, ww, bw, mask);
    k3a_stats<<<BSZ, 1024>>>();
    k3b_pool<<<dim3(NCHUNK, BSZ), 256>>>();
    k3c_reduce<<<BSZ, 256>>>();
    k4_final<<<1, 512>>>(Wc, bc, out);
}

// round 11
// speedup vs baseline: 1.3553x; 1.1526x over previous
#include <cuda_runtime.h>
#include <math.h>
#include <stdint.h>
#include <float.h>

#define BSZ 8
#define TT  8192
#define FF  1024
#define HH  256
#define OO  2
#define MTOK (BSZ * TT)   // 65536 tokens
#define NCHUNK 64

// ---- scratch (static device globals; no runtime allocation) ----
__device__ uint4  g_hb4[(size_t)MTOK * 32];   // 32 MB bf16 h, layout [mblk 512][kp 128][m 128]
__device__ float  g_logit[MTOK];
__device__ float2 g_stat[BSZ];
__device__ float  g_part[BSZ * NCHUNK * HH];
__device__ uint4  g_w1s[64 * 512];            // 512 KB: W1 bf16 [kt 64][kp 8][n 256]
__device__ uint4  g_wvs[16 * 512];            // 128 KB: Wv bf16 [blk 16][kp 32][n 64]
__device__ uint4  g_wus[16 * 512];            // 128 KB: Wu

// ---- helpers ----
__device__ __forceinline__ uint32_t pbf(float lo, float hi) {
    uint32_t r; asm("cvt.rn.bf16x2.f32 %0, %1, %2;" : "=r"(r) : "f"(hi), "f"(lo)); return r;
}
__device__ __forceinline__ float tanhfast(float x) {
    float y; asm("tanh.approx.f32 %0, %1;" : "=f"(y) : "f"(x)); return y;
}
__device__ __forceinline__ void mma16(float4& d, const uint32_t* a, uint32_t b0, uint32_t b1) {
    asm volatile("mma.sync.aligned.m16n8k16.row.col.f32.bf16.bf16.f32 "
        "{%0,%1,%2,%3}, {%4,%5,%6,%7}, {%8,%9}, {%0,%1,%2,%3};"
        : "+f"(d.x), "+f"(d.y), "+f"(d.z), "+f"(d.w)
        : "r"(a[0]), "r"(a[1]), "r"(a[2]), "r"(a[3]), "r"(b0), "r"(b1));
}
__device__ __forceinline__ uint32_t s2u(const void* p) {
    uint32_t a; asm("{ .reg .u64 t; cvta.to.shared.u64 t, %1; cvt.u32.u64 %0, t; }" : "=r"(a) : "l"(p));
    return a;
}
__device__ __forceinline__ void cpa16(uint32_t dst, const void* src) {
    asm volatile("cp.async.cg.shared.global [%0], [%1], 16;" :: "r"(dst), "l"(src));
}
__device__ __forceinline__ void cp_commit() { asm volatile("cp.async.commit_group;"); }
__device__ __forceinline__ void cp_wait0()  { asm volatile("cp.async.wait_group 0;"); }
__device__ __forceinline__ void cp_wait1()  { asm volatile("cp.async.wait_group 1;"); }
__device__ __forceinline__ void cp_wait2()  { asm volatile("cp.async.wait_group 2;"); }

// ============================================================================
// k1pre: W1 -> bf16 images [kt 64][kp 8][n 256].
// ============================================================================
__global__ __launch_bounds__(256)
void k1pre(const float* __restrict__ W1)
{
    const int kt = blockIdx.x, tid = threadIdx.x;
    const int kp = tid >> 5, n8 = (tid & 31) << 3;
    const float* r0 = W1 + (size_t)(kt * 16 + 2 * kp) * HH + n8;
    const float4 a0 = *(const float4*)(r0),        a1 = *(const float4*)(r0 + 4);
    const float4 b0 = *(const float4*)(r0 + HH),   b1 = *(const float4*)(r0 + HH + 4);
    g_w1s[kt * 512 + kp * 64 + (n8 >> 2)] =
        make_uint4(pbf(a0.x, b0.x), pbf(a0.y, b0.y), pbf(a0.z, b0.z), pbf(a0.w, b0.w));
    g_w1s[kt * 512 + kp * 64 + (n8 >> 2) + 1] =
        make_uint4(pbf(a1.x, b1.x), pbf(a1.y, b1.y), pbf(a1.z, b1.z), pbf(a1.w, b1.w));
}

// ============================================================================
// k2pre: Wv/Wu -> bf16 images [blk=nb*4+kh][kp 32][n 64].
// ============================================================================
__global__ __launch_bounds__(256)
void k2pre(const float* __restrict__ Wv, const float* __restrict__ Wu)
{
    const int blk = blockIdx.x, tid = threadIdx.x;
    const int nb = blk >> 2, kh = blk & 3;
    const int kp = tid >> 3, n8 = (tid & 7) << 3;
    const size_t off = (size_t)(kh * 64 + 2 * kp) * HH + nb * 64 + n8;
    {
        const float4 a0 = *(const float4*)(Wv + off),      a1 = *(const float4*)(Wv + off + 4);
        const float4 b0 = *(const float4*)(Wv + off + HH), b1 = *(const float4*)(Wv + off + HH + 4);
        g_wvs[blk * 512 + kp * 16 + (n8 >> 2)] =
            make_uint4(pbf(a0.x, b0.x), pbf(a0.y, b0.y), pbf(a0.z, b0.z), pbf(a0.w, b0.w));
        g_wvs[blk * 512 + kp * 16 + (n8 >> 2) + 1] =
            make_uint4(pbf(a1.x, b1.x), pbf(a1.y, b1.y), pbf(a1.z, b1.z), pbf(a1.w, b1.w));
    }
    {
        const float4 a0 = *(const float4*)(Wu + off),      a1 = *(const float4*)(Wu + off + 4);
        const float4 b0 = *(const float4*)(Wu + off + HH), b1 = *(const float4*)(Wu + off + HH + 4);
        g_wus[blk * 512 + kp * 16 + (n8 >> 2)] =
            make_uint4(pbf(a0.x, b0.x), pbf(a0.y, b0.y), pbf(a0.z, b0.z), pbf(a0.w, b0.w));
        g_wus[blk * 512 + kp * 16 + (n8 >> 2) + 1] =
            make_uint4(pbf(a1.x, b1.x), pbf(a1.y, b1.y), pbf(a1.z, b1.z), pbf(a1.w, b1.w));
    }
}

// ============================================================================
// K1: h = relu(bags @ W1 + b1). CTA 128x256, 512 thr.
// K=32 stages (2 MMA sub-blocks per barrier -> 32 barriers), 4-slot cp.async.
// A staged raw fp32, converted by the copying thread itself (no extra barrier).
// Epilogue writes ONLY bf16 g_hb4 ([mblk][kp 128][m 128]).
// ============================================================================
#define K1_ARW   36                 // raw A row words (32 data + 4 pad, 16B-aligned)
#define K1_ASTG  (128 * K1_ARW)     // 4608 words / stage
#define K1_BSTG  (16 * 264)         // 4224 words / stage
#define K1_BFA   (16 * 136)         // 2176 words / buffer
#define K1_SMEM  ((4 * K1_ASTG + 4 * K1_BSTG + 2 * K1_BFA) * 4)   // 158720 B
__global__ __launch_bounds__(512, 1)
void k1_gemm_relu(const float* __restrict__ A, const float* __restrict__ bias)
{
    extern __shared__ uint32_t sm1[];
    uint32_t* Araw = sm1;                       // [4][128][36] raw fp32
    uint32_t* Bst  = sm1 + 4 * K1_ASTG;         // [4][16][264] bf16 pairs
    uint32_t* bfA  = Bst + 4 * K1_BSTG;         // [2][16][136] bf16 pairs
    const uint32_t sAraw = s2u(Araw), sBst = s2u(Bst);

    const int tid = threadIdx.x;
    const int lane = tid & 31, wid = tid >> 5;
    const int wm = wid & 3, wn = wid >> 2;       // warp: rows wm*32, cols wn*64
    const int g = lane >> 2, tg = lane & 3;
    const size_t mBase = (size_t)blockIdx.x * 128;

    const int ar = tid >> 2, aq = tid & 3;       // A: row, k-quarter (8 k each)
    const float* aSrc = A + (mBase + ar) * FF + aq * 8;

    auto issue = [&](int kt2) {
        const int slot = kt2 & 3;
        const uint32_t aw = sAraw + (slot * K1_ASTG + ar * K1_ARW + aq * 8) * 4;
        cpa16(aw,      aSrc + kt2 * 32);
        cpa16(aw + 16, aSrc + kt2 * 32 + 4);
        const uint32_t bw_ = sBst + slot * (K1_BSTG * 4);
        cpa16(bw_ + ((tid >> 6) * 264 + (tid & 63) * 4) * 4,
              (const char*)g_w1s + (size_t)(2 * kt2) * 8192 + (size_t)tid * 16);
        cpa16(bw_ + ((8 + (tid >> 6)) * 264 + (tid & 63) * 4) * 4,
              (const char*)g_w1s + (size_t)(2 * kt2 + 1) * 8192 + (size_t)tid * 16);
        cp_commit();
    };
    issue(0); issue(1); issue(2);

    float4 acc[2][8];
    #pragma unroll
    for (int i = 0; i < 2; i++)
        #pragma unroll
        for (int j = 0; j < 8; j++) acc[i][j] = make_float4(0.f, 0.f, 0.f, 0.f);

    for (int kt2 = 0; kt2 < 32; kt2++) {
        if (kt2 <= 29) cp_wait2();
        else if (kt2 == 30) cp_wait1();
        else cp_wait0();

        const int slot = kt2 & 3;
        // convert own raw chunks -> bf16 [kp 16][136]
        {
            const uint32_t* rw = Araw + slot * K1_ASTG + ar * K1_ARW + aq * 8;
            const float4 v0 = *(const float4*)rw;
            const float4 v1 = *(const float4*)(rw + 4);
            uint32_t* bf = bfA + (kt2 & 1) * K1_BFA;
            bf[(aq * 4 + 0) * 136 + ar] = pbf(v0.x, v0.y);
            bf[(aq * 4 + 1) * 136 + ar] = pbf(v0.z, v0.w);
            bf[(aq * 4 + 2) * 136 + ar] = pbf(v1.x, v1.y);
            bf[(aq * 4 + 3) * 136 + ar] = pbf(v1.z, v1.w);
        }
        __syncthreads();     // publish bf16 A + B stage; proves slot (kt2-1)%4 drained
        if (kt2 + 3 < 32) issue(kt2 + 3);   // slot (kt2+3)%4 == (kt2-1)%4: safe

        const uint32_t* ap = bfA + (kt2 & 1) * K1_BFA;
        const uint32_t* bp = Bst + slot * K1_BSTG;
        #pragma unroll
        for (int s = 0; s < 2; s++) {
            const int r0 = s * 8 + tg, r1 = s * 8 + tg + 4;
            uint32_t afr[2][4];
            #pragma unroll
            for (int fm = 0; fm < 2; fm++) {
                const int m = wm * 32 + fm * 16 + g;
                afr[fm][0] = ap[r0 * 136 + m];  afr[fm][1] = ap[r0 * 136 + m + 8];
                afr[fm][2] = ap[r1 * 136 + m];  afr[fm][3] = ap[r1 * 136 + m + 8];
            }
            #pragma unroll
            for (int fn = 0; fn < 8; fn++) {
                const int n = wn * 64 + fn * 8 + g;
                const uint32_t b0 = bp[r0 * 264 + n], b1 = bp[r1 * 264 + n];
                mma16(acc[0][fn], afr[0], b0, b1);
                mma16(acc[1][fn], afr[1], b0, b1);
            }
        }
    }

    // epilogue: bias+relu -> bf16 g_hb4 only
    uint32_t* hbw = (uint32_t*)g_hb4 + (size_t)blockIdx.x * 16384;
    #pragma unroll
    for (int fm = 0; fm < 2; fm++) {
        #pragma unroll
        for (int half = 0; half < 2; half++) {
            const int mloc = wm * 32 + fm * 16 + g + half * 8;
            #pragma unroll
            for (int fn = 0; fn < 8; fn++) {
                const int c = wn * 64 + fn * 8 + tg * 2;
                const float v0 = half ? acc[fm][fn].z : acc[fm][fn].x;
                const float v1 = half ? acc[fm][fn].w : acc[fm][fn].y;
                const float h0 = fmaxf(v0 + bias[c], 0.f);
                const float h1 = fmaxf(v1 + bias[c + 1], 0.f);
                hbw[(c >> 1) * 128 + mloc] = pbf(h0, h1);
            }
        }
    }
}

// ============================================================================
// K2 (R10-identical, 68us): CTA 256 tokens, 512 thr, A resident, B double-buf.
// ============================================================================
#define K2_LDA 264
#define K2_AW  (128 * K2_LDA)   // 33792 words (132 KB)
#define K2_BW  (32 * 72)        // 2304 words per stage
#define K2_SMEM ((K2_AW + 4 * K2_BW) * 4)   // 172032 B
__global__ __launch_bounds__(512, 1)
void k2_gates(const float* __restrict__ bv, const float* __restrict__ bu,
              const float* __restrict__ ww, const float* __restrict__ bw,
              const unsigned char* __restrict__ mask)
{
    extern __shared__ uint32_t sm2[];
    uint32_t* As  = sm2;                  // [128 kp][264]
    uint32_t* BVs = sm2 + K2_AW;          // [2][32][72]
    uint32_t* BUs = BVs + 2 * K2_BW;
    __shared__ float red[2][256];
    const uint32_t sA = s2u(As), sBV = s2u(BVs), sBU = s2u(BUs);

    const int tid = threadIdx.x;
    const int lane = tid & 31, wid = tid >> 5;
    const int wm = wid & 7, wn = wid >> 3;       // warp: rows wm*32, cols wn*32
    const int g = lane >> 2, tg = lane & 3;
    const size_t m0 = (size_t)blockIdx.x * 256;
    const char* aImg = (const char*)g_hb4 + (size_t)(2 * blockIdx.x) * 65536;

    auto fillB = [&](int s, int p) {
        const int c = tid;
        const int row = c >> 4, col = c & 15;
        const uint32_t d = p * (K2_BW * 4) + row * (72 * 4) + col * 16;
        cpa16(sBV + d, (const char*)g_wvs + (size_t)s * 8192 + (size_t)c * 16);
        cpa16(sBU + d, (const char*)g_wus + (size_t)s * 8192 + (size_t)c * 16);
    };

    #pragma unroll
    for (int j = 0; j < 16; j++) {
        const int c = j * 512 + tid;
        const int q = c >> 12, r = c & 4095;
        const int kp = r >> 5, mw = (r & 31) << 2;
        cpa16(sA + (kp * K2_LDA + q * 128 + mw) * 4, aImg + (size_t)c * 16);
    }
    fillB(0, 0);
    cp_commit();

    float rowsum[4] = {0.f, 0.f, 0.f, 0.f};
    float4 accV[2][4], accU[2][4];

    for (int s = 0; s < 16; s++) {
        const int p = s & 1, nb = s >> 2, kh = s & 3;
        if (s < 15) { fillB(s + 1, p ^ 1); cp_commit(); cp_wait1(); }
        else cp_wait0();
        __syncthreads();

        if (kh == 0) {
            #pragma unroll
            for (int i = 0; i < 2; i++)
                #pragma unroll
                for (int j = 0; j < 4; j++) {
                    accV[i][j] = make_float4(0.f, 0.f, 0.f, 0.f);
                    accU[i][j] = make_float4(0.f, 0.f, 0.f, 0.f);
                }
        }

        const uint32_t* vp = BVs + p * K2_BW;
        const uint32_t* up = BUs + p * K2_BW;
        #pragma unroll
        for (int ks = 0; ks < 4; ks++) {
            const int r = ks * 8 + tg;
            const int ra = kh * 32 + r;
            uint32_t afr[2][4];
            #pragma unroll
            for (int fm = 0; fm < 2; fm++) {
                const int m = wm * 32 + fm * 16 + g;
                afr[fm][0] = As[ra * K2_LDA + m];       afr[fm][1] = As[ra * K2_LDA + m + 8];
                afr[fm][2] = As[(ra + 4) * K2_LDA + m]; afr[fm][3] = As[(ra + 4) * K2_LDA + m + 8];
            }
            #pragma unroll
            for (int fn = 0; fn < 4; fn++) {
                const int n = wn * 32 + fn * 8 + g;
                const uint32_t v0 = vp[r * 72 + n], v1 = vp[(r + 4) * 72 + n];
                const uint32_t u0 = up[r * 72 + n], u1 = up[(r + 4) * 72 + n];
                mma16(accV[0][fn], afr[0], v0, v1);
                mma16(accV[1][fn], afr[1], v0, v1);
                mma16(accU[0][fn], afr[0], u0, u1);
                mma16(accU[1][fn], afr[1], u0, u1);
            }
        }

        if (kh == 3) {
            #pragma unroll
            for (int fm = 0; fm < 2; fm++) {
                #pragma unroll
                for (int fn = 0; fn < 4; fn++) {
                    const int c = nb * 64 + wn * 32 + fn * 8 + tg * 2;
                    const float bv0 = bv[c], bv1 = bv[c + 1];
                    const float bu0 = bu[c], bu1 = bu[c + 1];
                    const float w0 = ww[c],  w1 = ww[c + 1];
                    const float4 av = accV[fm][fn], au = accU[fm][fn];
                    float v, u;
                    v = tanhfast(av.x + bv0); u = 0.5f * tanhfast(0.5f * (au.x + bu0)) + 0.5f;
                    rowsum[fm * 2 + 0] = fmaf(v * u, w0, rowsum[fm * 2 + 0]);
                    v = tanhfast(av.y + bv1); u = 0.5f * tanhfast(0.5f * (au.y + bu1)) + 0.5f;
                    rowsum[fm * 2 + 0] = fmaf(v * u, w1, rowsum[fm * 2 + 0]);
                    v = tanhfast(av.z + bv0); u = 0.5f * tanhfast(0.5f * (au.z + bu0)) + 0.5f;
                    rowsum[fm * 2 + 1] = fmaf(v * u, w0, rowsum[fm * 2 + 1]);
                    v = tanhfast(av.w + bv1); u = 0.5f * tanhfast(0.5f * (au.w + bu1)) + 0.5f;
                    rowsum[fm * 2 + 1] = fmaf(v * u, w1, rowsum[fm * 2 + 1]);
                }
            }
        }
        __syncthreads();
    }

    #pragma unroll
    for (int o = 1; o <= 2; o <<= 1)
        #pragma unroll
        for (int i = 0; i < 4; i++)
            rowsum[i] += __shfl_xor_sync(0xffffffffu, rowsum[i], o);

    if (tg == 0) {
        #pragma unroll
        for (int i = 0; i < 4; i++)
            red[wn][wm * 32 + (i >> 1) * 16 + (i & 1) * 8 + g] = rowsum[i];
    }
    __syncthreads();
    if (tid < 256) {
        const size_t m = m0 + tid;
        float val = red[0][tid] + red[1][tid] + bw[0];
        if (mask[m]) val = -1e30f;
        g_logit[m] = val;
    }
}

// ============================================================================
// K3a: per-batch softmax stats (unchanged).
// ============================================================================
__global__ __launch_bounds__(1024)
void k3a_stats()
{
    __shared__ float sred[1024];
    const int b = blockIdx.x, tid = threadIdx.x;
    const float* lg = g_logit + (size_t)b * TT;

    float lmax = -FLT_MAX;
    #pragma unroll
    for (int i = 0; i < 8; i++) lmax = fmaxf(lmax, lg[tid + i * 1024]);
    sred[tid] = lmax;
    __syncthreads();
    for (int s = 512; s > 0; s >>= 1) {
        if (tid < s) sred[tid] = fmaxf(sred[tid], sred[tid + s]);
        __syncthreads();
    }
    const float mx = sred[0];
    __syncthreads();

    float lsum = 0.f;
    #pragma unroll
    for (int i = 0; i < 8; i++) lsum += __expf(lg[tid + i * 1024] - mx);
    sred[tid] = lsum;
    __syncthreads();
    for (int s = 512; s > 0; s >>= 1) {
        if (tid < s) sred[tid] += sred[tid + s];
        __syncthreads();
    }
    if (tid == 0) g_stat[b] = make_float2(mx, 1.f / sred[0]);
}

// ============================================================================
// K3b: partial pooling from bf16 g_hb4. grid (64 blk, 8 b) x 256.
// Stage [kp 128][132] smem tile via cp.async (LDS.128 conflict-free), then
// thread (kp, m-half) accumulates 2 columns over 64 tokens.
// ============================================================================
#define K3B_LDH 132
#define K3B_SMEM (128 * K3B_LDH * 4)   // 67584 B
__global__ __launch_bounds__(256)
void k3b_pool()
{
    extern __shared__ uint32_t sh[];
    __shared__ float w[128];
    __shared__ float prt[256];
    const int b = blockIdx.y, ch = blockIdx.x, tid = threadIdx.x;
    const char* src = (const char*)g_hb4 + (size_t)(b * 64 + ch) * 65536;
    const uint32_t sbase = s2u(sh);

    #pragma unroll
    for (int j = 0; j < 16; j++) {
        const int c = j * 256 + tid;                   // 4096 uint4 chunks
        const int kp = c >> 5, mw = (c & 31) << 2;
        cpa16(sbase + (kp * K3B_LDH + mw) * 4, src + (size_t)c * 16);
    }
    cp_commit();

    const float2 st = g_stat[b];
    if (tid < 128)
        w[tid] = __expf(g_logit[(size_t)b * TT + ch * 128 + tid] - st.x) * st.y;
    cp_wait0();
    __syncthreads();

    const int kp = tid & 127, mh = tid >> 7;
    const uint32_t* row = sh + kp * K3B_LDH + mh * 64;
    const float* wp = &w[mh * 64];
    float alo = 0.f, ahi = 0.f;
    #pragma unroll
    for (int j = 0; j < 16; j++) {
        const uint4 u = *(const uint4*)(row + j * 4);
        const float w0 = wp[j * 4 + 0], w1 = wp[j * 4 + 1];
        const float w2 = wp[j * 4 + 2], w3 = wp[j * 4 + 3];
        alo = fmaf(w0, __uint_as_float(u.x << 16), alo);
        ahi = fmaf(w0, __uint_as_float(u.x & 0xFFFF0000u), ahi);
        alo = fmaf(w1, __uint_as_float(u.y << 16), alo);
        ahi = fmaf(w1, __uint_as_float(u.y & 0xFFFF0000u), ahi);
        alo = fmaf(w2, __uint_as_float(u.z << 16), alo);
        ahi = fmaf(w2, __uint_as_float(u.z & 0xFFFF0000u), ahi);
        alo = fmaf(w3, __uint_as_float(u.w << 16), alo);
        ahi = fmaf(w3, __uint_as_float(u.w & 0xFFFF0000u), ahi);
    }
    if (mh == 1) { prt[kp * 2] = alo; prt[kp * 2 + 1] = ahi; }
    __syncthreads();
    if (mh == 0) {
        float* dst = &g_part[((size_t)b * 64 + ch) * 256 + kp * 2];
        dst[0] = alo + prt[kp * 2];
        dst[1] = ahi + prt[kp * 2 + 1];
    }
}

// ============================================================================
// k3c_final: reduce 64 partials -> slide, then logits (fused K3c+K4).
// grid = 8 (one CTA per batch).
// ============================================================================
__global__ __launch_bounds__(256)
void k3c_final(const float* __restrict__ Wc, const float* __restrict__ bc,
               float* __restrict__ out)
{
    __shared__ float sred[256];
    const int b = blockIdx.x, tid = threadIdx.x;
    float s = 0.f;
    #pragma unroll 8
    for (int j = 0; j < 64; j++) s += g_part[((size_t)b * 64 + j) * 256 + tid];
    sred[tid] = s;
    __syncthreads();
    const int wid = tid >> 5, lane = tid & 31;
    if (wid < 2) {
        float d = 0.f;
        for (int c = lane; c < 256; c += 32) d = fmaf(sred[c], Wc[c * OO + wid], d);
        #pragma unroll
        for (int off = 16; off > 0; off >>= 1) d += __shfl_down_sync(0xffffffffu, d, off);
        if (lane == 0) out[b * OO + wid] = d + bc[wid];
    }
}

// ============================================================================
extern "C" void kernel_launch(void* const* d_in, const int* in_sizes, int n_in,
                              void* d_out, int out_size)
{
    const float*         bags = (const float*)d_in[0];
    const unsigned char* mask = (const unsigned char*)d_in[1];
    const float*         W1   = (const float*)d_in[2];
    const float*         b1   = (const float*)d_in[3];
    const float*         Wv   = (const float*)d_in[4];
    const float*         bv   = (const float*)d_in[5];
    const float*         Wu   = (const float*)d_in[6];
    const float*         bu   = (const float*)d_in[7];
    const float*         ww   = (const float*)d_in[8];
    const float*         bw   = (const float*)d_in[9];
    const float*         Wc   = (const float*)d_in[10];
    const float*         bc   = (const float*)d_in[11];
    float*               out  = (float*)d_out;

    cudaFuncSetAttribute(k1_gemm_relu, cudaFuncAttributeMaxDynamicSharedMemorySize, K1_SMEM);
    cudaFuncSetAttribute(k2_gates,     cudaFuncAttributeMaxDynamicSharedMemorySize, K2_SMEM);
    cudaFuncSetAttribute(k3b_pool,     cudaFuncAttributeMaxDynamicSharedMemorySize, K3B_SMEM);

    k1pre<<<64, 256>>>(W1);
    k2pre<<<16, 256>>>(Wv, Wu);
    k1_gemm_relu<<<MTOK / 128, 512, K1_SMEM>>>(bags, b1);
    k2_gates<<<MTOK / 256, 512, K2_SMEM>>>(bv, bu, ww, bw, mask);
    k3a_stats<<<BSZ, 1024>>>();
    k3b_pool<<<dim3(NCHUNK, BSZ), 256, K3B_SMEM>>>();
    k3c_final<<<BSZ, 256>>>(Wc, bc, out);
}